// round 1
// baseline (speedup 1.0000x reference)
#include <cuda_runtime.h>
#include <cuda_bf16.h>
#include <math.h>

#define BATCH 2
#define LSEQ 4096
#define DMODEL 1024
#define NSTATE 16
#define RRANK 64
#define MROWS (BATCH * LSEQ)   /* 8192 */

// Scratch (static device globals — no allocation at runtime)
__device__ float g_xconv[MROWS * DMODEL];      // (B,L,D)  32 MB
__device__ float g_tmp[MROWS * RRANK];         // (B*L, R)  2 MB
__device__ float g_dt[MROWS * DMODEL];         // (B,L,D)  32 MB
__device__ float g_bc[MROWS * NSTATE * 2];     // (B,L,N,2) interleaved B,C  1 MB

// ---------------------------------------------------------------------------
// Kernel 1: depthwise causal conv (K=4) + bias + SiLU
// ---------------------------------------------------------------------------
__global__ void conv_silu_kernel(const float* __restrict__ x,
                                 const float* __restrict__ w,
                                 const float* __restrict__ bias) {
    int gid = blockIdx.x * blockDim.x + threadIdx.x;
    if (gid >= MROWS * DMODEL) return;
    int d = gid % DMODEL;
    int row = gid / DMODEL;   // b*L + l
    int l = row % LSEQ;

    float acc = bias[d];
#pragma unroll
    for (int k = 0; k < 4; k++) {
        int ll = l - 3 + k;
        if (ll >= 0) acc = fmaf(x[gid + (k - 3) * DMODEL], w[d * 4 + k], acc);
    }
    // silu
    float s = acc / (1.0f + __expf(-acc));
    g_xconv[gid] = s;
}

// ---------------------------------------------------------------------------
// Kernel 2: fused projection GEMM  out(8192 x 96) = x_conv @ [W_dt1;W_B;W_C]^T
//   cols 0..63  -> g_tmp   (dt low-rank)
//   cols 64..79 -> g_bc[..][0]  (B_ssm)
//   cols 80..95 -> g_bc[..][1]  (C_ssm)
// BM=64, BN=96, BK=32, 256 threads, thread tile 4x6
// ---------------------------------------------------------------------------
__global__ void gemm1_kernel(const float* __restrict__ Wdt1,
                             const float* __restrict__ WB,
                             const float* __restrict__ WC) {
    __shared__ float As[32][66];    // [k][m]
    __shared__ float Bs[32][100];   // [k][j]

    int m0 = blockIdx.x * 64;
    int tid = threadIdx.x;
    int tx = tid % 16;          // col group: 6 cols each
    int ty = tid / 16;          // row group: 4 rows each

    float acc[4][6];
#pragma unroll
    for (int i = 0; i < 4; i++)
#pragma unroll
        for (int j = 0; j < 6; j++) acc[i][j] = 0.0f;

    for (int kk = 0; kk < DMODEL; kk += 32) {
        // A tile: 64 rows x 32 k
        for (int e = tid; e < 64 * 32; e += 256) {
            int r = e >> 5, c = e & 31;
            As[c][r] = g_xconv[(m0 + r) * DMODEL + kk + c];
        }
        // B tile: 96 rows (outputs) x 32 k
        for (int e = tid; e < 96 * 32; e += 256) {
            int j = e >> 5, c = e & 31;
            float v;
            if (j < 64)      v = Wdt1[j * DMODEL + kk + c];
            else if (j < 80) v = WB[(j - 64) * DMODEL + kk + c];
            else             v = WC[(j - 80) * DMODEL + kk + c];
            Bs[c][j] = v;
        }
        __syncthreads();

#pragma unroll
        for (int k = 0; k < 32; k++) {
            float a[4], b[6];
#pragma unroll
            for (int i = 0; i < 4; i++) a[i] = As[k][ty * 4 + i];
#pragma unroll
            for (int j = 0; j < 6; j++) b[j] = Bs[k][tx * 6 + j];
#pragma unroll
            for (int i = 0; i < 4; i++)
#pragma unroll
                for (int j = 0; j < 6; j++)
                    acc[i][j] = fmaf(a[i], b[j], acc[i][j]);
        }
        __syncthreads();
    }

#pragma unroll
    for (int i = 0; i < 4; i++) {
        int row = m0 + ty * 4 + i;
#pragma unroll
        for (int j = 0; j < 6; j++) {
            int col = tx * 6 + j;
            float v = acc[i][j];
            if (col < 64)       g_tmp[row * RRANK + col] = v;
            else if (col < 80)  g_bc[(row * NSTATE + (col - 64)) * 2 + 0] = v;
            else                g_bc[(row * NSTATE + (col - 80)) * 2 + 1] = v;
        }
    }
}

// ---------------------------------------------------------------------------
// Kernel 3: dt = softplus(g_tmp @ W_dt2^T + b_dt)   M=8192, N=1024, K=64
// BM=64, BN=64, BK=64 (single pass), 256 threads, thread tile 4x4
// ---------------------------------------------------------------------------
__global__ void gemm2_kernel(const float* __restrict__ Wdt2,
                             const float* __restrict__ bdt) {
    __shared__ float As[64][65];    // [k][m]
    __shared__ float Bs[64][68];    // [k][d]

    int m0 = blockIdx.x * 64;
    int n0 = blockIdx.y * 64;
    int tid = threadIdx.x;
    int tx = tid % 16;
    int ty = tid / 16;

    for (int e = tid; e < 64 * 64; e += 256) {
        int r = e >> 6, c = e & 63;
        As[c][r] = g_tmp[(m0 + r) * RRANK + c];
        Bs[c][r] = Wdt2[(n0 + r) * RRANK + c];
    }
    __syncthreads();

    float acc[4][4];
#pragma unroll
    for (int i = 0; i < 4; i++)
#pragma unroll
        for (int j = 0; j < 4; j++) acc[i][j] = 0.0f;

#pragma unroll
    for (int k = 0; k < 64; k++) {
        float a[4], b[4];
#pragma unroll
        for (int i = 0; i < 4; i++) a[i] = As[k][ty * 4 + i];
#pragma unroll
        for (int j = 0; j < 4; j++) b[j] = Bs[k][tx * 4 + j];
#pragma unroll
        for (int i = 0; i < 4; i++)
#pragma unroll
            for (int j = 0; j < 4; j++)
                acc[i][j] = fmaf(a[i], b[j], acc[i][j]);
    }

#pragma unroll
    for (int i = 0; i < 4; i++) {
        int row = m0 + ty * 4 + i;
#pragma unroll
        for (int j = 0; j < 4; j++) {
            int col = n0 + tx * 4 + j;
            float z = acc[i][j] + bdt[col];
            // softplus = max(z,0) + log1p(exp(-|z|))   (jax.nn.softplus)
            float sp = fmaxf(z, 0.0f) + log1pf(__expf(-fabsf(z)));
            g_dt[row * DMODEL + col] = sp;
        }
    }
}

// ---------------------------------------------------------------------------
// Kernel 4: selective scan.
// Thread layout: 16 lanes = 16 states of one (b,d) channel; warp = 2 channels.
// 2048 channels -> 128 CTAs x 256 threads (8 warps = 16 channels per CTA).
// ---------------------------------------------------------------------------
__global__ void scan_kernel(const float* __restrict__ A_log,
                            const float* __restrict__ Dp,
                            float* __restrict__ out) {
    int tid = threadIdx.x;
    int n = tid & 15;
    int c = blockIdx.x * 16 + (tid >> 4);   // channel = b*D + d
    int b = c / DMODEL;
    int d = c % DMODEL;

    float Aval = -__expf(A_log[d * NSTATE + n]);   // A[d][n] < 0
    float Dv = Dp[d];

    const float*  xp  = g_xconv + (size_t)b * LSEQ * DMODEL + d;
    const float*  dtp = g_dt    + (size_t)b * LSEQ * DMODEL + d;
    const float2* bcp = reinterpret_cast<const float2*>(g_bc)
                        + (size_t)b * LSEQ * NSTATE + n;
    float* op = out + (size_t)b * LSEQ * DMODEL + d;

    float h = 0.0f;

#pragma unroll 4
    for (int l = 0; l < LSEQ; l++) {
        float  xv  = __ldg(xp);  xp  += DMODEL;
        float  dtv = __ldg(dtp); dtp += DMODEL;
        float2 bc  = __ldg(bcp); bcp += NSTATE;

        // dtA = clip(dt*A, -10, 0); upper clip provably redundant (dt>0, A<0)
        float dtA = fmaxf(dtv * Aval, -10.0f);
        // A_bar = clip(exp(dtA), 0, 0.999); lower clip redundant (exp > 0)
        float a = fminf(__expf(dtA), 0.999f);
        // dtc = clip(dt, 0, 1); lower redundant
        float dtc = fminf(dtv, 1.0f);
        // B_bar = clip(dtc * B, -10, 10)
        float bb = fminf(fmaxf(dtc * bc.x, -10.0f), 10.0f);
        // h = clip(a*h + B_bar*x, -100, 100)
        h = fminf(fmaxf(fmaf(a, h, bb * xv), -100.0f), 100.0f);

        // y = sum_n h * C_n  (butterfly over the 16-lane state group)
        float y = h * bc.y;
        y += __shfl_xor_sync(0xffffffffu, y, 1, 32);
        y += __shfl_xor_sync(0xffffffffu, y, 2, 32);
        y += __shfl_xor_sync(0xffffffffu, y, 4, 32);
        y += __shfl_xor_sync(0xffffffffu, y, 8, 32);

        if (n == 0) {
            float yo = fminf(fmaxf(fmaf(Dv, xv, y), -50.0f), 50.0f);
            op[(size_t)l * DMODEL] = yo;
        }
    }
}

// ---------------------------------------------------------------------------
extern "C" void kernel_launch(void* const* d_in, const int* in_sizes, int n_in,
                              void* d_out, int out_size) {
    const float* x      = (const float*)d_in[0];
    const float* A_log  = (const float*)d_in[1];
    const float* D_par  = (const float*)d_in[2];
    const float* W_dt1  = (const float*)d_in[3];
    const float* W_dt2  = (const float*)d_in[4];
    const float* b_dt   = (const float*)d_in[5];
    const float* W_B    = (const float*)d_in[6];
    const float* W_C    = (const float*)d_in[7];
    const float* conv_w = (const float*)d_in[8];
    const float* conv_b = (const float*)d_in[9];
    float* out = (float*)d_out;

    (void)in_sizes; (void)n_in; (void)out_size;

    int total = MROWS * DMODEL;
    conv_silu_kernel<<<(total + 255) / 256, 256>>>(x, conv_w, conv_b);
    gemm1_kernel<<<MROWS / 64, 256>>>(W_dt1, W_B, W_C);
    gemm2_kernel<<<dim3(MROWS / 64, DMODEL / 64), 256>>>(W_dt2, b_dt);
    scan_kernel<<<(BATCH * DMODEL) / 16, 256>>>(A_log, D_par, out);
}

// round 2
// speedup vs baseline: 1.3960x; 1.3960x over previous
#include <cuda_runtime.h>
#include <cuda_bf16.h>
#include <math.h>

#define BATCH 2
#define LSEQ 4096
#define DMODEL 1024
#define NSTATE 16
#define RRANK 64
#define MROWS (BATCH * LSEQ)   /* 8192 */

// Scratch (static device globals — no allocation at runtime)
__device__ float  g_xconv[MROWS * DMODEL];     // (B,L,D)  32 MB  (for gemm1)
__device__ float2 g_xdt[MROWS * DMODEL];       // (B,L,D) packed {x_conv, dt} 64 MB
__device__ float  g_tmp[MROWS * RRANK];        // (B*L, R)  2 MB
__device__ float  g_bc[MROWS * NSTATE * 2];    // (B,L,N,2) interleaved B,C  1 MB

// ---------------------------------------------------------------------------
// Kernel 1: depthwise causal conv (K=4) + bias + SiLU
// ---------------------------------------------------------------------------
__global__ void conv_silu_kernel(const float* __restrict__ x,
                                 const float* __restrict__ w,
                                 const float* __restrict__ bias) {
    int gid = blockIdx.x * blockDim.x + threadIdx.x;
    if (gid >= MROWS * DMODEL) return;
    int d = gid % DMODEL;
    int row = gid / DMODEL;   // b*L + l
    int l = row % LSEQ;

    float acc = bias[d];
#pragma unroll
    for (int k = 0; k < 4; k++) {
        int ll = l - 3 + k;
        if (ll >= 0) acc = fmaf(x[gid + (k - 3) * DMODEL], w[d * 4 + k], acc);
    }
    // silu
    float s = acc / (1.0f + __expf(-acc));
    g_xconv[gid] = s;
    g_xdt[gid].x = s;
}

// ---------------------------------------------------------------------------
// Kernel 2: fused projection GEMM  out(8192 x 96) = x_conv @ [W_dt1;W_B;W_C]^T
//   cols 0..63  -> g_tmp   (dt low-rank)
//   cols 64..79 -> g_bc[..][0]  (B_ssm)
//   cols 80..95 -> g_bc[..][1]  (C_ssm)
// BM=64, BN=96, BK=32, 256 threads, thread tile 4x6
// ---------------------------------------------------------------------------
__global__ void gemm1_kernel(const float* __restrict__ Wdt1,
                             const float* __restrict__ WB,
                             const float* __restrict__ WC) {
    __shared__ float As[32][66];    // [k][m]
    __shared__ float Bs[32][100];   // [k][j]

    int m0 = blockIdx.x * 64;
    int tid = threadIdx.x;
    int tx = tid % 16;          // col group: 6 cols each
    int ty = tid / 16;          // row group: 4 rows each

    float acc[4][6];
#pragma unroll
    for (int i = 0; i < 4; i++)
#pragma unroll
        for (int j = 0; j < 6; j++) acc[i][j] = 0.0f;

    for (int kk = 0; kk < DMODEL; kk += 32) {
        // A tile: 64 rows x 32 k
        for (int e = tid; e < 64 * 32; e += 256) {
            int r = e >> 5, c = e & 31;
            As[c][r] = g_xconv[(m0 + r) * DMODEL + kk + c];
        }
        // B tile: 96 rows (outputs) x 32 k
        for (int e = tid; e < 96 * 32; e += 256) {
            int j = e >> 5, c = e & 31;
            float v;
            if (j < 64)      v = Wdt1[j * DMODEL + kk + c];
            else if (j < 80) v = WB[(j - 64) * DMODEL + kk + c];
            else             v = WC[(j - 80) * DMODEL + kk + c];
            Bs[c][j] = v;
        }
        __syncthreads();

#pragma unroll
        for (int k = 0; k < 32; k++) {
            float a[4], b[6];
#pragma unroll
            for (int i = 0; i < 4; i++) a[i] = As[k][ty * 4 + i];
#pragma unroll
            for (int j = 0; j < 6; j++) b[j] = Bs[k][tx * 6 + j];
#pragma unroll
            for (int i = 0; i < 4; i++)
#pragma unroll
                for (int j = 0; j < 6; j++)
                    acc[i][j] = fmaf(a[i], b[j], acc[i][j]);
        }
        __syncthreads();
    }

#pragma unroll
    for (int i = 0; i < 4; i++) {
        int row = m0 + ty * 4 + i;
#pragma unroll
        for (int j = 0; j < 6; j++) {
            int col = tx * 6 + j;
            float v = acc[i][j];
            if (col < 64)       g_tmp[row * RRANK + col] = v;
            else if (col < 80)  g_bc[(row * NSTATE + (col - 64)) * 2 + 0] = v;
            else                g_bc[(row * NSTATE + (col - 80)) * 2 + 1] = v;
        }
    }
}

// ---------------------------------------------------------------------------
// Kernel 3: dt = softplus(g_tmp @ W_dt2^T + b_dt)   M=8192, N=1024, K=64
// BM=64, BN=64, BK=64 (single pass), 256 threads, thread tile 4x4
// Writes dt into g_xdt[..].y (packed with x for the scan).
// ---------------------------------------------------------------------------
__global__ void gemm2_kernel(const float* __restrict__ Wdt2,
                             const float* __restrict__ bdt) {
    __shared__ float As[64][65];    // [k][m]
    __shared__ float Bs[64][68];    // [k][d]

    int m0 = blockIdx.x * 64;
    int n0 = blockIdx.y * 64;
    int tid = threadIdx.x;
    int tx = tid % 16;
    int ty = tid / 16;

    for (int e = tid; e < 64 * 64; e += 256) {
        int r = e >> 6, c = e & 63;
        As[c][r] = g_tmp[(m0 + r) * RRANK + c];
        Bs[c][r] = Wdt2[(n0 + r) * RRANK + c];
    }
    __syncthreads();

    float acc[4][4];
#pragma unroll
    for (int i = 0; i < 4; i++)
#pragma unroll
        for (int j = 0; j < 4; j++) acc[i][j] = 0.0f;

#pragma unroll
    for (int k = 0; k < 64; k++) {
        float a[4], b[4];
#pragma unroll
        for (int i = 0; i < 4; i++) a[i] = As[k][ty * 4 + i];
#pragma unroll
        for (int j = 0; j < 4; j++) b[j] = Bs[k][tx * 4 + j];
#pragma unroll
        for (int i = 0; i < 4; i++)
#pragma unroll
            for (int j = 0; j < 4; j++)
                acc[i][j] = fmaf(a[i], b[j], acc[i][j]);
    }

#pragma unroll
    for (int i = 0; i < 4; i++) {
        int row = m0 + ty * 4 + i;
#pragma unroll
        for (int j = 0; j < 4; j++) {
            int col = n0 + tx * 4 + j;
            float z = acc[i][j] + bdt[col];
            // softplus = max(z,0) + log1p(exp(-|z|))   (jax.nn.softplus)
            float sp = fmaxf(z, 0.0f) + log1pf(__expf(-fabsf(z)));
            g_xdt[row * DMODEL + col].y = sp;
        }
    }
}

// ---------------------------------------------------------------------------
// Kernel 4: selective scan, software-pipelined.
// Thread layout: 16 lanes = 16 states of one (b,d) channel; warp = 2 channels.
// 2048 channels -> 128 CTAs x 256 threads.
// Loads for tile t+1 are issued (into registers) before computing tile t.
// ---------------------------------------------------------------------------
#define SCAN_U 8

__global__ __launch_bounds__(256) void scan_kernel(
        const float* __restrict__ A_log,
        const float* __restrict__ Dp,
        float* __restrict__ out) {
    int tid = threadIdx.x;
    int n = tid & 15;
    int c = blockIdx.x * 16 + (tid >> 4);   // channel = b*D + d
    int b = c / DMODEL;
    int d = c % DMODEL;

    float Aval = -__expf(A_log[d * NSTATE + n]);   // A[d][n] < 0
    float Dv = Dp[d];

    const float2* xdtp = g_xdt + (size_t)b * LSEQ * DMODEL + d;
    const float2* bcp  = reinterpret_cast<const float2*>(g_bc)
                         + (size_t)b * LSEQ * NSTATE + n;
    float* op = out + (size_t)b * LSEQ * DMODEL + d;

    float h = 0.0f;

    // prologue: prefetch tile 0
    float2 xn[SCAN_U], bn[SCAN_U];
#pragma unroll
    for (int j = 0; j < SCAN_U; j++) {
        xn[j] = __ldg(xdtp + j * DMODEL);
        bn[j] = __ldg(bcp + j * NSTATE);
    }
    xdtp += SCAN_U * DMODEL;
    bcp  += SCAN_U * NSTATE;

    const int NTILES = LSEQ / SCAN_U;
    for (int t = 0; t < NTILES; t++) {
        // move prefetched tile into "current" regs
        float2 xc[SCAN_U], bc[SCAN_U];
#pragma unroll
        for (int j = 0; j < SCAN_U; j++) { xc[j] = xn[j]; bc[j] = bn[j]; }

        // prefetch next tile (covers the compute below)
        if (t + 1 < NTILES) {
#pragma unroll
            for (int j = 0; j < SCAN_U; j++) {
                xn[j] = __ldg(xdtp + j * DMODEL);
                bn[j] = __ldg(bcp + j * NSTATE);
            }
            xdtp += SCAN_U * DMODEL;
            bcp  += SCAN_U * NSTATE;
        }

        // compute SCAN_U sequential steps
#pragma unroll
        for (int j = 0; j < SCAN_U; j++) {
            float xv  = xc[j].x;
            float dtv = xc[j].y;

            // dtA = clip(dt*A, -10, 0); upper clip redundant (dt>0, A<0)
            float dtA = fmaxf(dtv * Aval, -10.0f);
            // A_bar = clip(exp(dtA), 0, 0.999); lower clip redundant
            float a = fminf(__expf(dtA), 0.999f);
            // dtc = clip(dt, 0, 1); lower redundant
            float dtc = fminf(dtv, 1.0f);
            // B_bar = clip(dtc * B, -10, 10)
            float bb = fminf(fmaxf(dtc * bc[j].x, -10.0f), 10.0f);
            // h = clip(a*h + B_bar*x, -100, 100)
            h = fminf(fmaxf(fmaf(a, h, bb * xv), -100.0f), 100.0f);

            // y = sum_n h * C_n  (butterfly over the 16-lane state group)
            float y = h * bc[j].y;
            y += __shfl_xor_sync(0xffffffffu, y, 1, 32);
            y += __shfl_xor_sync(0xffffffffu, y, 2, 32);
            y += __shfl_xor_sync(0xffffffffu, y, 4, 32);
            y += __shfl_xor_sync(0xffffffffu, y, 8, 32);

            if (n == 0) {
                float yo = fminf(fmaxf(fmaf(Dv, xv, y), -50.0f), 50.0f);
                op[(size_t)(t * SCAN_U + j) * DMODEL] = yo;
            }
        }
    }
}

// ---------------------------------------------------------------------------
extern "C" void kernel_launch(void* const* d_in, const int* in_sizes, int n_in,
                              void* d_out, int out_size) {
    const float* x      = (const float*)d_in[0];
    const float* A_log  = (const float*)d_in[1];
    const float* D_par  = (const float*)d_in[2];
    const float* W_dt1  = (const float*)d_in[3];
    const float* W_dt2  = (const float*)d_in[4];
    const float* b_dt   = (const float*)d_in[5];
    const float* W_B    = (const float*)d_in[6];
    const float* W_C    = (const float*)d_in[7];
    const float* conv_w = (const float*)d_in[8];
    const float* conv_b = (const float*)d_in[9];
    float* out = (float*)d_out;

    (void)in_sizes; (void)n_in; (void)out_size;

    int total = MROWS * DMODEL;
    conv_silu_kernel<<<(total + 255) / 256, 256>>>(x, conv_w, conv_b);
    gemm1_kernel<<<MROWS / 64, 256>>>(W_dt1, W_B, W_C);
    gemm2_kernel<<<dim3(MROWS / 64, DMODEL / 64), 256>>>(W_dt2, b_dt);
    scan_kernel<<<(BATCH * DMODEL) / 16, 256>>>(A_log, D_par, out);
}

// round 3
// speedup vs baseline: 1.5313x; 1.0969x over previous
#include <cuda_runtime.h>
#include <cuda_bf16.h>
#include <math.h>

#define BATCH 2
#define LSEQ 4096
#define DMODEL 1024
#define NSTATE 16
#define RRANK 64
#define MROWS (BATCH * LSEQ)   /* 8192 */

// Scratch (static device globals — no allocation at runtime)
__device__ float  g_xconv[MROWS * DMODEL];                  // (B,L,D)  32 MB
__device__ __align__(16) float2 g_xdt[MROWS * DMODEL];      // packed {x_conv, dt}  64 MB
__device__ float  g_tmp[MROWS * RRANK];                     // (B*L, R)  2 MB
__device__ float  g_bc[MROWS * NSTATE * 2];                 // (B,L,N,{B,C})  1 MB

// ---------------------------------------------------------------------------
// Kernel 1: depthwise causal conv (K=4) + bias + SiLU  -> g_xconv (contiguous)
// ---------------------------------------------------------------------------
__global__ void conv_silu_kernel(const float* __restrict__ x,
                                 const float* __restrict__ w,
                                 const float* __restrict__ bias) {
    int gid = blockIdx.x * blockDim.x + threadIdx.x;
    if (gid >= MROWS * DMODEL) return;
    int d = gid % DMODEL;
    int row = gid / DMODEL;   // b*L + l
    int l = row % LSEQ;

    float acc = bias[d];
#pragma unroll
    for (int k = 0; k < 4; k++) {
        int ll = l - 3 + k;
        if (ll >= 0) acc = fmaf(x[gid + (k - 3) * DMODEL], w[d * 4 + k], acc);
    }
    g_xconv[gid] = acc / (1.0f + __expf(-acc));   // silu
}

// ---------------------------------------------------------------------------
// Kernel 2: fused projection GEMM  out(8192 x 96) = x_conv @ [W_dt1;W_B;W_C]^T
//   cols 0..63  -> g_tmp (dt low-rank); 64..79 -> B_ssm; 80..95 -> C_ssm
// BM=64, BN=96, BK=32, 256 threads, thread tile 4x6
// ---------------------------------------------------------------------------
__global__ void gemm1_kernel(const float* __restrict__ Wdt1,
                             const float* __restrict__ WB,
                             const float* __restrict__ WC) {
    __shared__ float As[32][66];    // [k][m]
    __shared__ float Bs[32][100];   // [k][j]

    int m0 = blockIdx.x * 64;
    int tid = threadIdx.x;
    int tx = tid % 16;          // col group: 6 cols each
    int ty = tid / 16;          // row group: 4 rows each

    float acc[4][6];
#pragma unroll
    for (int i = 0; i < 4; i++)
#pragma unroll
        for (int j = 0; j < 6; j++) acc[i][j] = 0.0f;

    for (int kk = 0; kk < DMODEL; kk += 32) {
        for (int e = tid; e < 64 * 32; e += 256) {
            int r = e >> 5, c = e & 31;
            As[c][r] = g_xconv[(m0 + r) * DMODEL + kk + c];
        }
        for (int e = tid; e < 96 * 32; e += 256) {
            int j = e >> 5, c = e & 31;
            float v;
            if (j < 64)      v = Wdt1[j * DMODEL + kk + c];
            else if (j < 80) v = WB[(j - 64) * DMODEL + kk + c];
            else             v = WC[(j - 80) * DMODEL + kk + c];
            Bs[c][j] = v;
        }
        __syncthreads();

#pragma unroll
        for (int k = 0; k < 32; k++) {
            float a[4], b[6];
#pragma unroll
            for (int i = 0; i < 4; i++) a[i] = As[k][ty * 4 + i];
#pragma unroll
            for (int j = 0; j < 6; j++) b[j] = Bs[k][tx * 6 + j];
#pragma unroll
            for (int i = 0; i < 4; i++)
#pragma unroll
                for (int j = 0; j < 6; j++)
                    acc[i][j] = fmaf(a[i], b[j], acc[i][j]);
        }
        __syncthreads();
    }

#pragma unroll
    for (int i = 0; i < 4; i++) {
        int row = m0 + ty * 4 + i;
#pragma unroll
        for (int j = 0; j < 6; j++) {
            int col = tx * 6 + j;
            float v = acc[i][j];
            if (col < 64)       g_tmp[row * RRANK + col] = v;
            else if (col < 80)  g_bc[(row * NSTATE + (col - 64)) * 2 + 0] = v;
            else                g_bc[(row * NSTATE + (col - 80)) * 2 + 1] = v;
        }
    }
}

// ---------------------------------------------------------------------------
// Kernel 3: dt = softplus(g_tmp @ W_dt2^T + b_dt)   M=8192, N=1024, K=64
// Writes packed {x_conv, dt} into g_xdt with coalesced 16B stores.
// ---------------------------------------------------------------------------
__global__ void gemm2_kernel(const float* __restrict__ Wdt2,
                             const float* __restrict__ bdt) {
    __shared__ float As[64][65];    // [k][m]
    __shared__ float Bs[64][68];    // [k][d]

    int m0 = blockIdx.x * 64;
    int n0 = blockIdx.y * 64;
    int tid = threadIdx.x;
    int tx = tid % 16;
    int ty = tid / 16;

    for (int e = tid; e < 64 * 64; e += 256) {
        int r = e >> 6, c = e & 63;
        As[c][r] = g_tmp[(m0 + r) * RRANK + c];
        Bs[c][r] = Wdt2[(n0 + r) * RRANK + c];
    }
    __syncthreads();

    float acc[4][4];
#pragma unroll
    for (int i = 0; i < 4; i++)
#pragma unroll
        for (int j = 0; j < 4; j++) acc[i][j] = 0.0f;

#pragma unroll
    for (int k = 0; k < 64; k++) {
        float a[4], b[4];
#pragma unroll
        for (int i = 0; i < 4; i++) a[i] = As[k][ty * 4 + i];
#pragma unroll
        for (int j = 0; j < 4; j++) b[j] = Bs[k][tx * 4 + j];
#pragma unroll
        for (int i = 0; i < 4; i++)
#pragma unroll
            for (int j = 0; j < 4; j++)
                acc[i][j] = fmaf(a[i], b[j], acc[i][j]);
    }

#pragma unroll
    for (int i = 0; i < 4; i++) {
        int row = m0 + ty * 4 + i;
        int col0 = n0 + tx * 4;
        float4 xv = *reinterpret_cast<const float4*>(&g_xconv[row * DMODEL + col0]);
        float sp[4];
#pragma unroll
        for (int j = 0; j < 4; j++) {
            float z = acc[i][j] + bdt[col0 + j];
            sp[j] = fmaxf(z, 0.0f) + log1pf(__expf(-fabsf(z)));   // softplus
        }
        float4* dst = reinterpret_cast<float4*>(&g_xdt[row * DMODEL + col0]);
        dst[0] = make_float4(xv.x, sp[0], xv.y, sp[1]);
        dst[1] = make_float4(xv.z, sp[2], xv.w, sp[3]);
    }
}

// ---------------------------------------------------------------------------
// Kernel 4: selective scan, software-pipelined + round-batched reduction.
// 16 lanes = 16 states of one (b,d) channel; warp = 2 channels.
// Per 8-step tile: phase 1 = h recurrence (serial, short chain),
// phase 2 = butterfly reduction with ROUND loop outer (8 independent shfl
// chains in flight), phase 3 = predicated stores.
// ---------------------------------------------------------------------------
#define SCAN_U 8

__global__ __launch_bounds__(256) void scan_kernel(
        const float* __restrict__ A_log,
        const float* __restrict__ Dp,
        float* __restrict__ out) {
    int tid = threadIdx.x;
    int n = tid & 15;
    int c = blockIdx.x * 16 + (tid >> 4);   // channel = b*D + d
    int b = c / DMODEL;
    int d = c % DMODEL;

    float Aval = -__expf(A_log[d * NSTATE + n]);   // A[d][n] < 0
    float Dv = Dp[d];

    const float2* xdtp = g_xdt + (size_t)b * LSEQ * DMODEL + d;
    const float2* bcp  = reinterpret_cast<const float2*>(g_bc)
                         + (size_t)b * LSEQ * NSTATE + n;
    float* op = out + (size_t)b * LSEQ * DMODEL + d;

    float h = 0.0f;

    // prologue: prefetch tile 0
    float2 xn[SCAN_U], bn[SCAN_U];
#pragma unroll
    for (int j = 0; j < SCAN_U; j++) {
        xn[j] = __ldg(xdtp + j * DMODEL);
        bn[j] = __ldg(bcp + j * NSTATE);
    }
    xdtp += SCAN_U * DMODEL;
    bcp  += SCAN_U * NSTATE;

    const int NTILES = LSEQ / SCAN_U;
    for (int t = 0; t < NTILES; t++) {
        float2 xc[SCAN_U], bc[SCAN_U];
#pragma unroll
        for (int j = 0; j < SCAN_U; j++) { xc[j] = xn[j]; bc[j] = bn[j]; }

        // prefetch next tile (covers compute below)
        if (t + 1 < NTILES) {
#pragma unroll
            for (int j = 0; j < SCAN_U; j++) {
                xn[j] = __ldg(xdtp + j * DMODEL);
                bn[j] = __ldg(bcp + j * NSTATE);
            }
            xdtp += SCAN_U * DMODEL;
            bcp  += SCAN_U * NSTATE;
        }

        // ---- phase 1: h recurrence; produce p[j] = h_j * C_j ----
        float p[SCAN_U];
#pragma unroll
        for (int j = 0; j < SCAN_U; j++) {
            float xv  = xc[j].x;
            float dtv = xc[j].y;
            // dtA = clip(dt*A, -10, 0); upper clip redundant (dt>0, A<0)
            float dtA = fmaxf(dtv * Aval, -10.0f);
            // A_bar = clip(exp(dtA), 0, 0.999); lower clip redundant
            float a = fminf(__expf(dtA), 0.999f);
            // dtc = clip(dt, 0, 1); lower redundant
            float dtc = fminf(dtv, 1.0f);
            // B_bar = clip(dtc*B, -10, 10)
            float bb = fminf(fmaxf(dtc * bc[j].x, -10.0f), 10.0f);
            // h = clip(a*h + B_bar*x, -100, 100)
            h = fminf(fmaxf(fmaf(a, h, bb * xv), -100.0f), 100.0f);
            p[j] = h * bc[j].y;
        }

        // ---- phase 2: butterfly reduce over 16-lane state group,
        //      round-major so 8 shfl chains stay independent ----
#pragma unroll
        for (int s = 1; s < 16; s <<= 1) {
#pragma unroll
            for (int j = 0; j < SCAN_U; j++)
                p[j] += __shfl_xor_sync(0xffffffffu, p[j], s, 32);
        }

        // ---- phase 3: stores (lane 0 of each state group) ----
        if (n == 0) {
#pragma unroll
            for (int j = 0; j < SCAN_U; j++) {
                float yo = fminf(fmaxf(fmaf(Dv, xc[j].x, p[j]), -50.0f), 50.0f);
                op[(size_t)(t * SCAN_U + j) * DMODEL] = yo;
            }
        }
    }
}

// ---------------------------------------------------------------------------
extern "C" void kernel_launch(void* const* d_in, const int* in_sizes, int n_in,
                              void* d_out, int out_size) {
    const float* x      = (const float*)d_in[0];
    const float* A_log  = (const float*)d_in[1];
    const float* D_par  = (const float*)d_in[2];
    const float* W_dt1  = (const float*)d_in[3];
    const float* W_dt2  = (const float*)d_in[4];
    const float* b_dt   = (const float*)d_in[5];
    const float* W_B    = (const float*)d_in[6];
    const float* W_C    = (const float*)d_in[7];
    const float* conv_w = (const float*)d_in[8];
    const float* conv_b = (const float*)d_in[9];
    float* out = (float*)d_out;

    (void)in_sizes; (void)n_in; (void)out_size;

    int total = MROWS * DMODEL;
    conv_silu_kernel<<<(total + 255) / 256, 256>>>(x, conv_w, conv_b);
    gemm1_kernel<<<MROWS / 64, 256>>>(W_dt1, W_B, W_C);
    gemm2_kernel<<<dim3(MROWS / 64, DMODEL / 64), 256>>>(W_dt2, b_dt);
    scan_kernel<<<(BATCH * DMODEL) / 16, 256>>>(A_log, D_par, out);
}